// round 4
// baseline (speedup 1.0000x reference)
#include <cuda_runtime.h>
#include <math.h>

// ---- problem constants (fixed shapes) ----
#define T_TOK  4096     // B * Q_LEN tokens
#define HIDDEN 4096
#define NH     32
#define HD     128
#define B_SEQ  8
#define Q_LEN  512
#define BS_PG  64       // paged-cache block size
#define NBLK   16

// ---- scratch (device globals; allocation-free) ----
__device__ float g_q[(size_t)T_TOK * HIDDEN];
__device__ float g_k[(size_t)T_TOK * HIDDEN];
__device__ float g_v[(size_t)T_TOK * HIDDEN];
__device__ float g_attn[(size_t)T_TOK * HIDDEN];

// ============================================================================
// SGEMM: C[4096,4096] = A[4096,4096] @ B[4096,4096], fp32 row-major.
// 128x128 block tile, BK=8, 256 threads, 8x8 micro-tile, register prefetch.
// ============================================================================
__global__ __launch_bounds__(256) void sgemm4096(
    const float* __restrict__ A, const float* __restrict__ B,
    float* __restrict__ C) {
  const int K = 4096, N = 4096;
  __shared__ float As[8][128];   // transposed A tile: As[k][m]
  __shared__ float Bs[8][128];   // Bs[k][n]
  int tid = threadIdx.x;
  int cRow = blockIdx.y, cCol = blockIdx.x;
  int tr = tid >> 4, tc = tid & 15;
  const float* Ab = A + (size_t)cRow * 128 * K;
  const float* Bb = B + cCol * 128;
  int aRow = tid >> 1, aCol = (tid & 1) * 4;
  int bRow = tid >> 5, bCol = (tid & 31) * 4;

  float acc[8][8];
#pragma unroll
  for (int i = 0; i < 8; i++)
#pragma unroll
    for (int j = 0; j < 8; j++) acc[i][j] = 0.f;

  float4 av = *(const float4*)(Ab + (size_t)aRow * K + aCol);
  float4 bv = *(const float4*)(Bb + (size_t)bRow * N + bCol);

  for (int k0 = 0; k0 < K; k0 += 8) {
    As[aCol + 0][aRow] = av.x;
    As[aCol + 1][aRow] = av.y;
    As[aCol + 2][aRow] = av.z;
    As[aCol + 3][aRow] = av.w;
    *(float4*)(&Bs[bRow][bCol]) = bv;
    __syncthreads();
    if (k0 + 8 < K) {
      av = *(const float4*)(Ab + (size_t)aRow * K + (k0 + 8) + aCol);
      bv = *(const float4*)(Bb + (size_t)(k0 + 8 + bRow) * N + bCol);
    }
#pragma unroll
    for (int kk = 0; kk < 8; kk++) {
      float4 a0 = *(float4*)(&As[kk][tr * 8]);
      float4 a1 = *(float4*)(&As[kk][tr * 8 + 4]);
      float4 b0 = *(float4*)(&Bs[kk][tc * 8]);
      float4 b1 = *(float4*)(&Bs[kk][tc * 8 + 4]);
      float ra[8] = {a0.x, a0.y, a0.z, a0.w, a1.x, a1.y, a1.z, a1.w};
      float rb[8] = {b0.x, b0.y, b0.z, b0.w, b1.x, b1.y, b1.z, b1.w};
#pragma unroll
      for (int i = 0; i < 8; i++)
#pragma unroll
        for (int j = 0; j < 8; j++)
          acc[i][j] = fmaf(ra[i], rb[j], acc[i][j]);
    }
    __syncthreads();
  }

  float* Cb = C + (size_t)cRow * 128 * N + cCol * 128;
#pragma unroll
  for (int i = 0; i < 8; i++) {
#pragma unroll
    for (int j = 0; j < 8; j += 4) {
      float4 v = make_float4(acc[i][j], acc[i][j + 1], acc[i][j + 2], acc[i][j + 3]);
      *(float4*)(Cb + (size_t)(tr * 8 + i) * N + tc * 8 + j) = v;
    }
  }
}

// ============================================================================
// RoPE (in-place on g_q, g_k). One thread per (token, head, j<64) pair.
// out[d]    = x[d]*cos(th_d)    - x[d+64]*sin(th_d)      (d < 64)
// out[d+64] = x[d+64]*cos(th_d) + x[d]*sin(th_d)
// ============================================================================
__global__ void rope_kernel(float* __restrict__ q, float* __restrict__ k,
                            const int* __restrict__ pos_ids) {
  int idx = blockIdx.x * 256 + threadIdx.x;
  if (idx >= T_TOK * NH * 64) return;
  int j = idx & 63;
  int th = idx >> 6;       // t*NH + h
  int t = th >> 5;         // /NH
  float pos = (float)pos_ids[t];
  float inv = expf(-logf(10000.f) * (float)(2 * j) * (1.f / 128.f));
  float ang = pos * inv;
  float s, c;
  sincosf(ang, &s, &c);
  size_t base = (size_t)th * 128;
  float q1 = q[base + j], q2 = q[base + j + 64];
  q[base + j]      = q1 * c - q2 * s;
  q[base + j + 64] = q2 * c + q1 * s;
  float k1 = k[base + j], k2 = k[base + j + 64];
  k[base + j]      = k1 * c - k2 * s;
  k[base + j + 64] = k2 * c + k1 * s;
}

// ============================================================================
// Flash attention, fp32. One CTA per (q-tile of 64, head, seq).
// KV tiles of 64: kt<8 -> history from paged cache (tile == one page),
// kt>=8 -> new tokens from g_k/g_v (already RoPE'd). Online softmax.
// ============================================================================
#define LDQ 132
#define LDK 129
#define LDV 128
#define LDSS 65
#define OFF_Q 0
#define OFF_K 8448
#define OFF_V 16704
#define OFF_S 24896
#define OFF_M 29056
#define OFF_L 29120
#define OFF_A 29184
#define OFF_P 29248
#define ATTN_SMEM_FLOATS 29312

__global__ __launch_bounds__(256) void attn_kernel(
    const float* __restrict__ k_cache, const float* __restrict__ v_cache,
    const int* __restrict__ block_tab, const int* __restrict__ pos_ids,
    const int* __restrict__ kv_len) {
  extern __shared__ float sm[];
  float* Qs = sm + OFF_Q;
  float* Ks = sm + OFF_K;
  float* Vs = sm + OFF_V;
  float* Ss = sm + OFF_S;
  float* Ms = sm + OFF_M;
  float* Ls = sm + OFF_L;
  float* Al = sm + OFF_A;
  int* Ps = (int*)(sm + OFF_P);

  int qt = blockIdx.x, h = blockIdx.y, b = blockIdx.z;
  int tid = threadIdx.x;
  int tr = tid >> 4, tc = tid & 15;
  int t_base = b * Q_LEN + qt * 64;

  // Load Q tile [64 x 128] into smem (padded rows).
  for (int i = tid; i < 64 * 32; i += 256) {
    int r = i >> 5, d4 = (i & 31) * 4;
    float4 v = *(const float4*)(g_q + (size_t)(t_base + r) * HIDDEN + h * HD + d4);
    *(float4*)(&Qs[r * LDQ + d4]) = v;
  }
  if (tid < 64) {
    Ps[tid] = pos_ids[t_base + tid];
    Ms[tid] = -1e30f;
    Ls[tid] = 0.f;
  }
  __syncthreads();

  int kvl = kv_len[b];
  int maxp = 0;
  for (int i = 0; i < 64; i++) maxp = max(maxp, Ps[i]);
  int nt = min(maxp / 64 + 1, (kvl + 63) / 64);
  if (nt > 16) nt = 16;

  float acc[4][8];
#pragma unroll
  for (int i = 0; i < 4; i++)
#pragma unroll
    for (int j = 0; j < 8; j++) acc[i][j] = 0.f;

  const float scale = 0.08838834764831845f;  // 1/sqrt(128)

  for (int kt = 0; kt < nt; kt++) {
    // ---- load K/V tile [64 x 128] ----
    const float *kbase, *vbase;
    if (kt < 8) {
      int blk = block_tab[b * NBLK + kt];
      size_t off = ((size_t)blk * BS_PG * NH + h) * HD;  // [blk, slot=0, h, 0]
      kbase = k_cache + off;
      vbase = v_cache + off;
    } else {
      size_t off = (size_t)(b * Q_LEN + (kt - 8) * 64) * HIDDEN + h * HD;
      kbase = g_k + off;
      vbase = g_v + off;
    }
    for (int i = tid; i < 64 * 32; i += 256) {
      int r = i >> 5, d4 = (i & 31) * 4;
      float4 kv4 = *(const float4*)(kbase + (size_t)r * HIDDEN + d4);
      Ks[r * LDK + d4 + 0] = kv4.x;
      Ks[r * LDK + d4 + 1] = kv4.y;
      Ks[r * LDK + d4 + 2] = kv4.z;
      Ks[r * LDK + d4 + 3] = kv4.w;
      float4 vv4 = *(const float4*)(vbase + (size_t)r * HIDDEN + d4);
      *(float4*)(&Vs[r * LDV + d4]) = vv4;
    }
    __syncthreads();

    // ---- S = Q K^T (64x64), 4x4 micro-tile per thread ----
    float accs[4][4];
#pragma unroll
    for (int i = 0; i < 4; i++)
#pragma unroll
      for (int j = 0; j < 4; j++) accs[i][j] = 0.f;
#pragma unroll 4
    for (int d = 0; d < 128; d++) {
      float ra[4], rb[4];
#pragma unroll
      for (int i = 0; i < 4; i++) ra[i] = Qs[(tr * 4 + i) * LDQ + d];
#pragma unroll
      for (int j = 0; j < 4; j++) rb[j] = Ks[(tc * 4 + j) * LDK + d];
#pragma unroll
      for (int i = 0; i < 4; i++)
#pragma unroll
        for (int j = 0; j < 4; j++)
          accs[i][j] = fmaf(ra[i], rb[j], accs[i][j]);
    }
    // mask + scale + stage into smem
#pragma unroll
    for (int i = 0; i < 4; i++) {
      int r = tr * 4 + i;
      int qp = Ps[r];
#pragma unroll
      for (int j = 0; j < 4; j++) {
        int kvp = kt * 64 + tc * 4 + j;
        float sv = accs[i][j] * scale;
        if (kvp > qp || kvp >= kvl) sv = -1e30f;
        Ss[r * LDSS + tc * 4 + j] = sv;
      }
    }
    __syncthreads();

    // ---- online softmax row update: 4 threads per row ----
    {
      int row = tid >> 2, q4 = tid & 3;
      float mx = -1e30f;
#pragma unroll
      for (int i = 0; i < 16; i++) mx = fmaxf(mx, Ss[row * LDSS + q4 * 16 + i]);
      mx = fmaxf(mx, __shfl_xor_sync(0xffffffffu, mx, 1));
      mx = fmaxf(mx, __shfl_xor_sync(0xffffffffu, mx, 2));
      float m_old = Ms[row];
      float m_new = fmaxf(m_old, mx);
      float sum = 0.f;
#pragma unroll
      for (int i = 0; i < 16; i++) {
        float p = __expf(Ss[row * LDSS + q4 * 16 + i] - m_new);
        Ss[row * LDSS + q4 * 16 + i] = p;
        sum += p;
      }
      sum += __shfl_xor_sync(0xffffffffu, sum, 1);
      sum += __shfl_xor_sync(0xffffffffu, sum, 2);
      if (q4 == 0) {
        float alpha = __expf(m_old - m_new);
        Al[row] = alpha;
        Ls[row] = Ls[row] * alpha + sum;
        Ms[row] = m_new;
      }
    }
    __syncthreads();

    // ---- rescale acc, then O += P @ V (4x8 micro-tile) ----
#pragma unroll
    for (int i = 0; i < 4; i++) {
      float a = Al[tr * 4 + i];
#pragma unroll
      for (int j = 0; j < 8; j++) acc[i][j] *= a;
    }
#pragma unroll 2
    for (int kk = 0; kk < 64; kk++) {
      float rp[4];
#pragma unroll
      for (int i = 0; i < 4; i++) rp[i] = Ss[(tr * 4 + i) * LDSS + kk];
      float4 v0 = *(float4*)(&Vs[kk * LDV + tc * 8]);
      float4 v1 = *(float4*)(&Vs[kk * LDV + tc * 8 + 4]);
      float rv[8] = {v0.x, v0.y, v0.z, v0.w, v1.x, v1.y, v1.z, v1.w};
#pragma unroll
      for (int i = 0; i < 4; i++)
#pragma unroll
        for (int j = 0; j < 8; j++)
          acc[i][j] = fmaf(rp[i], rv[j], acc[i][j]);
    }
    __syncthreads();
  }

  // ---- normalize and write to g_attn ----
#pragma unroll
  for (int i = 0; i < 4; i++) {
    int r = tr * 4 + i;
    float inv_l = 1.f / Ls[r];
    float* dst = g_attn + (size_t)(t_base + r) * HIDDEN + h * HD + tc * 8;
    float4 o0 = make_float4(acc[i][0] * inv_l, acc[i][1] * inv_l,
                            acc[i][2] * inv_l, acc[i][3] * inv_l);
    float4 o1 = make_float4(acc[i][4] * inv_l, acc[i][5] * inv_l,
                            acc[i][6] * inv_l, acc[i][7] * inv_l);
    *(float4*)(dst) = o0;
    *(float4*)(dst + 4) = o1;
  }
}

// ============================================================================
extern "C" void kernel_launch(void* const* d_in, const int* in_sizes, int n_in,
                              void* d_out, int out_size) {
  const float* hidden = (const float*)d_in[0];
  const float* Wq = (const float*)d_in[1];
  const float* Wk = (const float*)d_in[2];
  const float* Wv = (const float*)d_in[3];
  const float* Wo = (const float*)d_in[4];
  const float* kc = (const float*)d_in[5];
  const float* vc = (const float*)d_in[6];
  const int* btab = (const int*)d_in[7];
  const int* pos = (const int*)d_in[8];
  const int* kvlen = (const int*)d_in[9];
  float* out = (float*)d_out;

  float *q, *k, *v, *attn;
  cudaGetSymbolAddress((void**)&q, g_q);
  cudaGetSymbolAddress((void**)&k, g_k);
  cudaGetSymbolAddress((void**)&v, g_v);
  cudaGetSymbolAddress((void**)&attn, g_attn);

  dim3 gg(32, 32);
  sgemm4096<<<gg, 256>>>(hidden, Wq, q);
  sgemm4096<<<gg, 256>>>(hidden, Wk, k);
  sgemm4096<<<gg, 256>>>(hidden, Wv, v);

  rope_kernel<<<(T_TOK * NH * 64 + 255) / 256, 256>>>(q, k, pos);

  cudaFuncSetAttribute(attn_kernel, cudaFuncAttributeMaxDynamicSharedMemorySize,
                       ATTN_SMEM_FLOATS * 4);
  dim3 ga(8, NH, B_SEQ);  // (q-tile, head, seq)
  attn_kernel<<<ga, 256, ATTN_SMEM_FLOATS * 4>>>(kc, vc, btab, pos, kvlen);

  sgemm4096<<<gg, 256>>>(attn, Wo, out);
}

// round 5
// speedup vs baseline: 2.4530x; 2.4530x over previous
#include <cuda_runtime.h>
#include <math.h>
#include <stdint.h>

// ---- problem constants (fixed shapes) ----
#define T_TOK  4096     // B * Q_LEN tokens
#define HIDDEN 4096
#define NH     32
#define HD     128
#define B_SEQ  8
#define Q_LEN  512
#define BS_PG  64       // paged-cache block size
#define NBLK   16

// ---- scratch (device globals; allocation-free) ----
__device__ float g_q[(size_t)T_TOK * HIDDEN];
__device__ float g_k[(size_t)T_TOK * HIDDEN];
__device__ float g_v[(size_t)T_TOK * HIDDEN];
__device__ float g_attn[(size_t)T_TOK * HIDDEN];

// ============================================================================
// TF32 tensor-core GEMM: C[4096,4096] = A @ B, fp32 in/out.
// CTA tile 128x128, BK=16, 4-stage cp.async pipeline, 256 threads (8 warps,
// warp grid 2(m) x 4(n), warp tile 64x32, mma.m16n8k8 tf32).
// Fragments rounded fp32->tf32 with cvt.rna (unbiased) before MMA.
// ============================================================================
#define GBM 128
#define GBN 128
#define GBK 16
#define GSTAGES 4
#define GLDA 20                      // As row stride (floats): conflict-free
#define GLDB 136                     // Bs row stride (floats): conflict-free
#define AS_STAGE (GBM * GLDA)        // 2560 floats
#define BS_STAGE (GBK * GLDB)        // 2176 floats
#define STAGE_FLOATS (AS_STAGE + BS_STAGE)   // 4736 floats = 18944 B
#define GEMM_SMEM_BYTES (STAGE_FLOATS * GSTAGES * 4)  // 75776 B

__device__ __forceinline__ uint32_t smem_u32(const void* p) {
  return (uint32_t)__cvta_generic_to_shared(p);
}
__device__ __forceinline__ void cp_async16(uint32_t dst, const void* src) {
  asm volatile("cp.async.cg.shared.global [%0], [%1], 16;\n" ::"r"(dst), "l"(src));
}
__device__ __forceinline__ uint32_t f2tf(float x) {
  uint32_t u;
  asm("cvt.rna.tf32.f32 %0, %1;\n" : "=r"(u) : "f"(x));
  return u;
}
__device__ __forceinline__ void mma_tf32(float& d0, float& d1, float& d2, float& d3,
                                         uint32_t a0, uint32_t a1, uint32_t a2, uint32_t a3,
                                         uint32_t b0, uint32_t b1) {
  asm volatile(
      "mma.sync.aligned.m16n8k8.row.col.f32.tf32.tf32.f32 "
      "{%0,%1,%2,%3},{%4,%5,%6,%7},{%8,%9},{%0,%1,%2,%3};\n"
      : "+f"(d0), "+f"(d1), "+f"(d2), "+f"(d3)
      : "r"(a0), "r"(a1), "r"(a2), "r"(a3), "r"(b0), "r"(b1));
}

__device__ __forceinline__ void gemm_load_stage(
    float* smem, int s, int kt, int m0, int n0, int tid,
    const float* __restrict__ A, const float* __restrict__ B) {
  const int K = 4096, N = 4096;
  float* As = smem + s * STAGE_FLOATS;
  float* Bs = As + AS_STAGE;
  int k0 = kt * GBK;
  // A: 128 rows x 16 floats = 512 16B-chunks; 2 per thread
#pragma unroll
  for (int i = 0; i < 2; i++) {
    int c = tid + i * 256;
    int r = c >> 2, kc = (c & 3) * 4;
    cp_async16(smem_u32(As + r * GLDA + kc),
               A + (size_t)(m0 + r) * K + k0 + kc);
  }
  // B: 16 rows x 128 floats = 512 16B-chunks; 2 per thread
#pragma unroll
  for (int i = 0; i < 2; i++) {
    int c = tid + i * 256;
    int kr = c >> 5, nc = (c & 31) * 4;
    cp_async16(smem_u32(Bs + kr * GLDB + nc),
               B + (size_t)(k0 + kr) * N + n0 + nc);
  }
}

__global__ __launch_bounds__(256, 1) void gemm_tf32(
    const float* __restrict__ A, const float* __restrict__ B,
    float* __restrict__ C) {
  extern __shared__ float smem[];
  const int K = 4096, N = 4096;
  int tid = threadIdx.x;
  int m0 = blockIdx.y * GBM, n0 = blockIdx.x * GBN;
  int lane = tid & 31, warp = tid >> 5;
  int g = lane >> 2, t = lane & 3;
  int wm = (warp & 1) * 64;   // warp m-offset (2 warps over 128 rows)
  int wn = (warp >> 1) * 32;  // warp n-offset (4 warps over 128 cols)

  float acc[4][4][4];
#pragma unroll
  for (int mi = 0; mi < 4; mi++)
#pragma unroll
    for (int ni = 0; ni < 4; ni++)
#pragma unroll
      for (int e = 0; e < 4; e++) acc[mi][ni][e] = 0.f;

  const int NT = K / GBK;  // 256
  // prologue: fill STAGES-1 pipeline slots
#pragma unroll
  for (int s = 0; s < GSTAGES - 1; s++) {
    gemm_load_stage(smem, s, s, m0, n0, tid, A, B);
    asm volatile("cp.async.commit_group;\n");
  }

  for (int kt = 0; kt < NT; kt++) {
    asm volatile("cp.async.wait_group %0;\n" ::"n"(GSTAGES - 2));
    __syncthreads();
    int pf = kt + GSTAGES - 1;
    if (pf < NT) gemm_load_stage(smem, pf % GSTAGES, pf, m0, n0, tid, A, B);
    asm volatile("cp.async.commit_group;\n");

    float* As = smem + (kt % GSTAGES) * STAGE_FLOATS;
    float* Bs = As + AS_STAGE;
#pragma unroll
    for (int kk = 0; kk < GBK; kk += 8) {
      uint32_t a[4][4], b[4][2];
#pragma unroll
      for (int mi = 0; mi < 4; mi++) {
        int r = wm + mi * 16 + g;
        a[mi][0] = f2tf(As[r * GLDA + kk + t]);
        a[mi][1] = f2tf(As[(r + 8) * GLDA + kk + t]);
        a[mi][2] = f2tf(As[r * GLDA + kk + t + 4]);
        a[mi][3] = f2tf(As[(r + 8) * GLDA + kk + t + 4]);
      }
#pragma unroll
      for (int ni = 0; ni < 4; ni++) {
        int c = wn + ni * 8 + g;
        b[ni][0] = f2tf(Bs[(kk + t) * GLDB + c]);
        b[ni][1] = f2tf(Bs[(kk + t + 4) * GLDB + c]);
      }
#pragma unroll
      for (int mi = 0; mi < 4; mi++)
#pragma unroll
        for (int ni = 0; ni < 4; ni++)
          mma_tf32(acc[mi][ni][0], acc[mi][ni][1], acc[mi][ni][2], acc[mi][ni][3],
                   a[mi][0], a[mi][1], a[mi][2], a[mi][3],
                   b[ni][0], b[ni][1]);
    }
  }

  // epilogue
#pragma unroll
  for (int mi = 0; mi < 4; mi++) {
#pragma unroll
    for (int ni = 0; ni < 4; ni++) {
      int r = m0 + wm + mi * 16 + g;
      int c = n0 + wn + ni * 8 + 2 * t;
      *(float2*)(C + (size_t)r * N + c) =
          make_float2(acc[mi][ni][0], acc[mi][ni][1]);
      *(float2*)(C + (size_t)(r + 8) * N + c) =
          make_float2(acc[mi][ni][2], acc[mi][ni][3]);
    }
  }
}

// ============================================================================
// RoPE (in-place on g_q, g_k). One thread per (token, head, j<64) pair.
// ============================================================================
__global__ void rope_kernel(float* __restrict__ q, float* __restrict__ k,
                            const int* __restrict__ pos_ids) {
  int idx = blockIdx.x * 256 + threadIdx.x;
  if (idx >= T_TOK * NH * 64) return;
  int j = idx & 63;
  int th = idx >> 6;       // t*NH + h
  int t = th >> 5;         // /NH
  float pos = (float)pos_ids[t];
  float inv = expf(-logf(10000.f) * (float)(2 * j) * (1.f / 128.f));
  float ang = pos * inv;
  float s, c;
  sincosf(ang, &s, &c);
  size_t base = (size_t)th * 128;
  float q1 = q[base + j], q2 = q[base + j + 64];
  q[base + j]      = q1 * c - q2 * s;
  q[base + j + 64] = q2 * c + q1 * s;
  float k1 = k[base + j], k2 = k[base + j + 64];
  k[base + j]      = k1 * c - k2 * s;
  k[base + j + 64] = k2 * c + k1 * s;
}

// ============================================================================
// Flash attention, fp32. One CTA per (q-tile of 64, head, seq).
// KV tiles of 64: kt<8 -> history from paged cache (tile == one page),
// kt>=8 -> new tokens from g_k/g_v (already RoPE'd). Online softmax.
// ============================================================================
#define LDQ 132
#define LDK 129
#define LDV 128
#define LDSS 65
#define OFF_Q 0
#define OFF_K 8448
#define OFF_V 16704
#define OFF_S 24896
#define OFF_M 29056
#define OFF_L 29120
#define OFF_A 29184
#define OFF_P 29248
#define ATTN_SMEM_FLOATS 29312

__global__ __launch_bounds__(256) void attn_kernel(
    const float* __restrict__ k_cache, const float* __restrict__ v_cache,
    const int* __restrict__ block_tab, const int* __restrict__ pos_ids,
    const int* __restrict__ kv_len) {
  extern __shared__ float sm[];
  float* Qs = sm + OFF_Q;
  float* Ks = sm + OFF_K;
  float* Vs = sm + OFF_V;
  float* Ss = sm + OFF_S;
  float* Ms = sm + OFF_M;
  float* Ls = sm + OFF_L;
  float* Al = sm + OFF_A;
  int* Ps = (int*)(sm + OFF_P);

  int qt = blockIdx.x, h = blockIdx.y, b = blockIdx.z;
  int tid = threadIdx.x;
  int tr = tid >> 4, tc = tid & 15;
  int t_base = b * Q_LEN + qt * 64;

  for (int i = tid; i < 64 * 32; i += 256) {
    int r = i >> 5, d4 = (i & 31) * 4;
    float4 v = *(const float4*)(g_q + (size_t)(t_base + r) * HIDDEN + h * HD + d4);
    *(float4*)(&Qs[r * LDQ + d4]) = v;
  }
  if (tid < 64) {
    Ps[tid] = pos_ids[t_base + tid];
    Ms[tid] = -1e30f;
    Ls[tid] = 0.f;
  }
  __syncthreads();

  int kvl = kv_len[b];
  int maxp = 0;
  for (int i = 0; i < 64; i++) maxp = max(maxp, Ps[i]);
  int nt = min(maxp / 64 + 1, (kvl + 63) / 64);
  if (nt > 16) nt = 16;

  float acc[4][8];
#pragma unroll
  for (int i = 0; i < 4; i++)
#pragma unroll
    for (int j = 0; j < 8; j++) acc[i][j] = 0.f;

  const float scale = 0.08838834764831845f;  // 1/sqrt(128)

  for (int kt = 0; kt < nt; kt++) {
    const float *kbase, *vbase;
    if (kt < 8) {
      int blk = block_tab[b * NBLK + kt];
      size_t off = ((size_t)blk * BS_PG * NH + h) * HD;
      kbase = k_cache + off;
      vbase = v_cache + off;
    } else {
      size_t off = (size_t)(b * Q_LEN + (kt - 8) * 64) * HIDDEN + h * HD;
      kbase = g_k + off;
      vbase = g_v + off;
    }
    for (int i = tid; i < 64 * 32; i += 256) {
      int r = i >> 5, d4 = (i & 31) * 4;
      float4 kv4 = *(const float4*)(kbase + (size_t)r * HIDDEN + d4);
      Ks[r * LDK + d4 + 0] = kv4.x;
      Ks[r * LDK + d4 + 1] = kv4.y;
      Ks[r * LDK + d4 + 2] = kv4.z;
      Ks[r * LDK + d4 + 3] = kv4.w;
      float4 vv4 = *(const float4*)(vbase + (size_t)r * HIDDEN + d4);
      *(float4*)(&Vs[r * LDV + d4]) = vv4;
    }
    __syncthreads();

    float accs[4][4];
#pragma unroll
    for (int i = 0; i < 4; i++)
#pragma unroll
      for (int j = 0; j < 4; j++) accs[i][j] = 0.f;
#pragma unroll 4
    for (int d = 0; d < 128; d++) {
      float ra[4], rb[4];
#pragma unroll
      for (int i = 0; i < 4; i++) ra[i] = Qs[(tr * 4 + i) * LDQ + d];
#pragma unroll
      for (int j = 0; j < 4; j++) rb[j] = Ks[(tc * 4 + j) * LDK + d];
#pragma unroll
      for (int i = 0; i < 4; i++)
#pragma unroll
        for (int j = 0; j < 4; j++)
          accs[i][j] = fmaf(ra[i], rb[j], accs[i][j]);
    }
#pragma unroll
    for (int i = 0; i < 4; i++) {
      int r = tr * 4 + i;
      int qp = Ps[r];
#pragma unroll
      for (int j = 0; j < 4; j++) {
        int kvp = kt * 64 + tc * 4 + j;
        float sv = accs[i][j] * scale;
        if (kvp > qp || kvp >= kvl) sv = -1e30f;
        Ss[r * LDSS + tc * 4 + j] = sv;
      }
    }
    __syncthreads();

    {
      int row = tid >> 2, q4 = tid & 3;
      float mx = -1e30f;
#pragma unroll
      for (int i = 0; i < 16; i++) mx = fmaxf(mx, Ss[row * LDSS + q4 * 16 + i]);
      mx = fmaxf(mx, __shfl_xor_sync(0xffffffffu, mx, 1));
      mx = fmaxf(mx, __shfl_xor_sync(0xffffffffu, mx, 2));
      float m_old = Ms[row];
      float m_new = fmaxf(m_old, mx);
      float sum = 0.f;
#pragma unroll
      for (int i = 0; i < 16; i++) {
        float p = __expf(Ss[row * LDSS + q4 * 16 + i] - m_new);
        Ss[row * LDSS + q4 * 16 + i] = p;
        sum += p;
      }
      sum += __shfl_xor_sync(0xffffffffu, sum, 1);
      sum += __shfl_xor_sync(0xffffffffu, sum, 2);
      if (q4 == 0) {
        float alpha = __expf(m_old - m_new);
        Al[row] = alpha;
        Ls[row] = Ls[row] * alpha + sum;
        Ms[row] = m_new;
      }
    }
    __syncthreads();

#pragma unroll
    for (int i = 0; i < 4; i++) {
      float a = Al[tr * 4 + i];
#pragma unroll
      for (int j = 0; j < 8; j++) acc[i][j] *= a;
    }
#pragma unroll 2
    for (int kk = 0; kk < 64; kk++) {
      float rp[4];
#pragma unroll
      for (int i = 0; i < 4; i++) rp[i] = Ss[(tr * 4 + i) * LDSS + kk];
      float4 v0 = *(float4*)(&Vs[kk * LDV + tc * 8]);
      float4 v1 = *(float4*)(&Vs[kk * LDV + tc * 8 + 4]);
      float rv[8] = {v0.x, v0.y, v0.z, v0.w, v1.x, v1.y, v1.z, v1.w};
#pragma unroll
      for (int i = 0; i < 4; i++)
#pragma unroll
        for (int j = 0; j < 8; j++)
          acc[i][j] = fmaf(rp[i], rv[j], acc[i][j]);
    }
    __syncthreads();
  }

#pragma unroll
  for (int i = 0; i < 4; i++) {
    int r = tr * 4 + i;
    float inv_l = 1.f / Ls[r];
    float* dst = g_attn + (size_t)(t_base + r) * HIDDEN + h * HD + tc * 8;
    float4 o0 = make_float4(acc[i][0] * inv_l, acc[i][1] * inv_l,
                            acc[i][2] * inv_l, acc[i][3] * inv_l);
    float4 o1 = make_float4(acc[i][4] * inv_l, acc[i][5] * inv_l,
                            acc[i][6] * inv_l, acc[i][7] * inv_l);
    *(float4*)(dst) = o0;
    *(float4*)(dst + 4) = o1;
  }
}

// ============================================================================
extern "C" void kernel_launch(void* const* d_in, const int* in_sizes, int n_in,
                              void* d_out, int out_size) {
  const float* hidden = (const float*)d_in[0];
  const float* Wq = (const float*)d_in[1];
  const float* Wk = (const float*)d_in[2];
  const float* Wv = (const float*)d_in[3];
  const float* Wo = (const float*)d_in[4];
  const float* kc = (const float*)d_in[5];
  const float* vc = (const float*)d_in[6];
  const int* btab = (const int*)d_in[7];
  const int* pos = (const int*)d_in[8];
  const int* kvlen = (const int*)d_in[9];
  float* out = (float*)d_out;

  float *q, *k, *v, *attn;
  cudaGetSymbolAddress((void**)&q, g_q);
  cudaGetSymbolAddress((void**)&k, g_k);
  cudaGetSymbolAddress((void**)&v, g_v);
  cudaGetSymbolAddress((void**)&attn, g_attn);

  cudaFuncSetAttribute(gemm_tf32, cudaFuncAttributeMaxDynamicSharedMemorySize,
                       GEMM_SMEM_BYTES);
  dim3 gg(32, 32);
  gemm_tf32<<<gg, 256, GEMM_SMEM_BYTES>>>(hidden, Wq, q);
  gemm_tf32<<<gg, 256, GEMM_SMEM_BYTES>>>(hidden, Wk, k);
  gemm_tf32<<<gg, 256, GEMM_SMEM_BYTES>>>(hidden, Wv, v);

  rope_kernel<<<(T_TOK * NH * 64 + 255) / 256, 256>>>(q, k, pos);

  cudaFuncSetAttribute(attn_kernel, cudaFuncAttributeMaxDynamicSharedMemorySize,
                       ATTN_SMEM_FLOATS * 4);
  dim3 ga(8, NH, B_SEQ);  // (q-tile, head, seq)
  attn_kernel<<<ga, 256, ATTN_SMEM_FLOATS * 4>>>(kc, vc, btab, pos, kvlen);

  gemm_tf32<<<gg, 256, GEMM_SMEM_BYTES>>>(attn, Wo, out);
}